// round 14
// baseline (speedup 1.0000x reference)
#include <cuda_runtime.h>
#include <cuda_fp16.h>
#include <math.h>
#include <stdint.h>

#define B_ 8
#define L_ 4096
#define D_ 768
#define Y_ 2048
#define NLB 64                  // l-blocks (L/64)
#define NTILES 8192             // 64 lblk * 16 yblk * 8 b

// ---------------- device scratch (no allocations allowed) ----------------
__device__ __half g_Xh[(size_t)B_ * L_ * D_];
__device__ __half g_Uh[(size_t)Y_ * D_];
__device__ __half g_Fh[(size_t)Y_ * D_];
__device__ float g_pm[(size_t)B_ * Y_ * NLB];
__device__ float g_ps[(size_t)B_ * Y_ * NLB];
__device__ float g_pn[(size_t)B_ * Y_ * NLB];
__device__ float g_y[(size_t)B_ * Y_];
__device__ float g_loss;

// ---------------- helpers ----------------
__device__ __forceinline__ uint32_t smem_u32(const void* p) {
    uint32_t a;
    asm("{ .reg .u64 t; cvta.to.shared.u64 t, %1; cvt.u32.u64 %0, t; }" : "=r"(a) : "l"(p));
    return a;
}
#define SWZ128(x) ((x) ^ (((x) >> 3) & 0x70))

#define CP16(dst, src) \
    asm volatile("cp.async.cg.shared.global [%0], [%1], 16;" :: "r"(dst), "l"(src))
#define CPCOMMIT() asm volatile("cp.async.commit_group;" ::: "memory")
#define CPWAIT1() asm volatile("cp.async.wait_group 1;" ::: "memory")
#define CPWAIT0() asm volatile("cp.async.wait_group 0;" ::: "memory")

__device__ __forceinline__ void ldsm_x4(uint32_t* r, uint32_t addr) {
    asm volatile("ldmatrix.sync.aligned.m8n8.x4.shared.b16 {%0,%1,%2,%3}, [%4];"
        : "=r"(r[0]), "=r"(r[1]), "=r"(r[2]), "=r"(r[3]) : "r"(addr));
}
#define MMA_F16(d, a, b0, b1)                                                 \
    asm volatile("mma.sync.aligned.m16n8k16.row.col.f32.f16.f16.f32 "         \
        "{%0,%1,%2,%3}, {%4,%5,%6,%7}, {%8,%9}, {%0,%1,%2,%3};"               \
        : "+f"((d)[0]), "+f"((d)[1]), "+f"((d)[2]), "+f"((d)[3])              \
        : "r"((a)[0]), "r"((a)[1]), "r"((a)[2]), "r"((a)[3]),                 \
          "r"(b0), "r"(b1))

// ---------------- fp32 -> fp16 convert ----------------
__global__ void cvt_f16(const float* __restrict__ in, __half* __restrict__ out, int n4) {
    int i = blockIdx.x * blockDim.x + threadIdx.x;
    if (i >= n4) return;
    float4 v = ((const float4*)in)[i];
    ((__half2*)out)[i * 2 + 0] = __half2(__float2half_rn(v.x), __float2half_rn(v.y));
    ((__half2*)out)[i * 2 + 1] = __half2(__float2half_rn(v.z), __float2half_rn(v.w));
}

// ------- persistent dual GEMM (fp16), 2 CTAs/SM, 128y x 64l tiles ----------
// 256 threads, warp grid 4y x 2l, warp tile 32y x 32l dual-output.
// Stage = k-chunk 64: U 16KB, F 16KB, X 8KB = 40KB. 2-stage ring.
#define T16K 16384
#define X8K 8192
#define XOFF (2 * T16K)            // 32768
#define STAGE_B 40960
#define PART_OFF (2 * STAGE_B)     // 81920
#define SMEM_TOT (PART_OFF + 3 * 128 * 2 * 4)   // 84992

__device__ __forceinline__ void issue_stage(uint32_t sb, int ls,
                                            int tid, int stride) {
    const int tl = ls / 12, ks = ls - tl * 12;
    const int t = blockIdx.x + tl * stride;
    const int lblk = t & 63, yblk = (t >> 6) & 15, b = t >> 10;
    const __half* usrc = g_Uh + (size_t)(yblk * 128) * D_ + ks * 64;
    const __half* fsrc = g_Fh + (size_t)(yblk * 128) * D_ + ks * 64;
    const __half* xsrc = g_Xh + ((size_t)b * L_ + lblk * 64) * D_ + ks * 64;
    const uint32_t bufb = (uint32_t)(ls & 1) * STAGE_B;
#pragma unroll
    for (int j = 0; j < 10; j++) {
        const int gi = j * 256 + tid;          // 0..2559
        if (gi < 2048) {
            const int tt = gi >> 10;           // 0=U, 1=F
            const int ci = gi & 1023;
            const int row = ci >> 3, c16 = ci & 7;
            const __half* base = (tt == 0) ? usrc : fsrc;
            const char* src = (const char*)(base + (size_t)row * D_) + c16 * 16;
            const uint32_t dst = sb + bufb + tt * T16K + SWZ128(row * 128 + c16 * 16);
            CP16(dst, src);
        } else {
            const int ci = gi - 2048;          // 0..511
            const int row = ci >> 3, c16 = ci & 7;
            const char* src = (const char*)(xsrc + (size_t)row * D_) + c16 * 16;
            const uint32_t dst = sb + bufb + XOFF + SWZ128(row * 128 + c16 * 16);
            CP16(dst, src);
        }
    }
    CPCOMMIT();
}

__global__ void __launch_bounds__(256, 2)
gemm_kernel() {
    extern __shared__ char smem[];
    const uint32_t sb = smem_u32(smem);
    float* partm = (float*)(smem + PART_OFF);          // [128][2]
    float* parts = partm + 128 * 2;
    float* partn = parts + 128 * 2;

    const int tid = threadIdx.x, lane = tid & 31, wid = tid >> 5;
    const int stride = gridDim.x;
    const int myN = (NTILES - blockIdx.x + stride - 1) / stride;
    const int total = 12 * myN;

    const int my = (wid & 3) * 32;
    const int nl = (wid >> 2) * 32;        // 0 or 32
    const int wcol = wid >> 2;             // 0..1

    // unswizzled byte offsets; SWZ128 applied per load (swizzle not additive)
    const uint32_t aByte = (uint32_t)((my + (lane & 15)) * 128 + ((lane >> 4) << 4));
    const uint32_t bByte = (uint32_t)((nl + (lane & 7) + ((lane >> 4) & 1) * 8) * 128
                                      + (((lane >> 3) & 1) << 4));

    float att[2][4][4], tac[2][4][4];
#pragma unroll
    for (int mt = 0; mt < 2; mt++)
#pragma unroll
        for (int nt = 0; nt < 4; nt++)
#pragma unroll
            for (int r = 0; r < 4; r++) { att[mt][nt][r] = 0.f; tac[mt][nt][r] = 0.f; }

    issue_stage(sb, 0, tid, stride);
    if (total > 1) issue_stage(sb, 1, tid, stride);

    for (int ls = 0; ls < total; ls++) {
        if (ls == total - 1) { CPWAIT0(); } else { CPWAIT1(); }
        __syncthreads();
        const uint32_t bufo = sb + (uint32_t)(ls & 1) * STAGE_B;

#pragma unroll
        for (int kk = 0; kk < 4; kk++) {
            const uint32_t kq32 = (uint32_t)(kk * 32);
            uint32_t bh0[4], bh1[4];
            {
                const uint32_t sw0 = SWZ128(bByte + kq32);
                const uint32_t sw1 = SWZ128(bByte + (uint32_t)(16 * 128) + kq32);
                ldsm_x4(bh0, bufo + XOFF + sw0);
                ldsm_x4(bh1, bufo + XOFF + sw1);
            }
#pragma unroll
            for (int mt = 0; mt < 2; mt++) {
                const uint32_t swa = SWZ128(aByte + (uint32_t)(mt * 16 * 128) + kq32);
                uint32_t uh[4], fh[4];
                ldsm_x4(uh, bufo + 0 * T16K + swa);
                ldsm_x4(fh, bufo + 1 * T16K + swa);
                MMA_F16(att[mt][0], uh, bh0[0], bh0[1]);
                MMA_F16(att[mt][1], uh, bh0[2], bh0[3]);
                MMA_F16(att[mt][2], uh, bh1[0], bh1[1]);
                MMA_F16(att[mt][3], uh, bh1[2], bh1[3]);
                MMA_F16(tac[mt][0], fh, bh0[0], bh0[1]);
                MMA_F16(tac[mt][1], fh, bh0[2], bh0[3]);
                MMA_F16(tac[mt][2], fh, bh1[0], bh1[1]);
                MMA_F16(tac[mt][3], fh, bh1[2], bh1[3]);
            }
        }
        __syncthreads();
        if (ls + 2 < total) issue_stage(sb, ls + 2, tid, stride);

        if ((ls % 12) == 11) {
            // ---- register-level partial softmax for this 128x64 tile ----
            const int t = blockIdx.x + (ls / 12) * stride;
            const int lblk = t & 63, yblk = (t >> 6) & 15, b = t >> 10;
#pragma unroll
            for (int mt = 0; mt < 2; mt++) {
#pragma unroll
                for (int half = 0; half < 2; half++) {
                    float a[8], tv[8];
#pragma unroll
                    for (int nt = 0; nt < 4; nt++)
#pragma unroll
                        for (int j = 0; j < 2; j++) {
                            a[nt * 2 + j] = att[mt][nt][half * 2 + j];
                            tv[nt * 2 + j] = tac[mt][nt][half * 2 + j];
                        }
                    float m = a[0];
#pragma unroll
                    for (int j = 1; j < 8; j++) m = fmaxf(m, a[j]);
                    m = fmaxf(m, __shfl_xor_sync(0xffffffffu, m, 1));
                    m = fmaxf(m, __shfl_xor_sync(0xffffffffu, m, 2));
                    float S = 0.f, N = 0.f;
#pragma unroll
                    for (int j = 0; j < 8; j++) {
                        const float e = __expf(a[j] - m);
                        S += e;
                        N += e * tv[j];
                    }
                    S += __shfl_xor_sync(0xffffffffu, S, 1);
                    S += __shfl_xor_sync(0xffffffffu, S, 2);
                    N += __shfl_xor_sync(0xffffffffu, N, 1);
                    N += __shfl_xor_sync(0xffffffffu, N, 2);
                    if ((lane & 3) == 0) {
                        const int row = my + mt * 16 + half * 8 + (lane >> 2);
                        partm[row * 2 + wcol] = m;
                        parts[row * 2 + wcol] = S;
                        partn[row * 2 + wcol] = N;
                    }
                }
            }
            __syncthreads();
            if (tid < 128) {
                const float m0 = partm[tid * 2 + 0], m1 = partm[tid * 2 + 1];
                const float gm = fmaxf(m0, m1);
                const float e0 = __expf(m0 - gm), e1 = __expf(m1 - gm);
                const float S = parts[tid * 2 + 0] * e0 + parts[tid * 2 + 1] * e1;
                const float N = partn[tid * 2 + 0] * e0 + partn[tid * 2 + 1] * e1;
                const size_t idx = ((size_t)b * Y_ + yblk * 128 + tid) * NLB + lblk;
                g_pm[idx] = gm; g_ps[idx] = S; g_pn[idx] = N;
            }
#pragma unroll
            for (int mt = 0; mt < 2; mt++)
#pragma unroll
                for (int nt = 0; nt < 4; nt++)
#pragma unroll
                    for (int r = 0; r < 4; r++) {
                        att[mt][nt][r] = 0.f; tac[mt][nt][r] = 0.f;
                    }
        }
    }
}

// ---------------- reduce 64 partials per row -> logits ----------------
__global__ void __launch_bounds__(256)
reduce_kernel(const float* __restrict__ bias) {
    const int rr = blockIdx.x * 8 + (threadIdx.x >> 5);
    const int lane = threadIdx.x & 31;
    const size_t base = (size_t)rr * NLB;
    const float ma = g_pm[base + lane], mb = g_pm[base + 32 + lane];
    float gm = fmaxf(ma, mb);
#pragma unroll
    for (int s = 16; s > 0; s >>= 1) gm = fmaxf(gm, __shfl_xor_sync(0xffffffffu, gm, s));
    const float sa = __expf(ma - gm), sb2 = __expf(mb - gm);
    float S = g_ps[base + lane] * sa + g_ps[base + 32 + lane] * sb2;
    float N = g_pn[base + lane] * sa + g_pn[base + 32 + lane] * sb2;
#pragma unroll
    for (int s = 16; s > 0; s >>= 1) {
        S += __shfl_xor_sync(0xffffffffu, S, s);
        N += __shfl_xor_sync(0xffffffffu, N, s);
    }
    if (lane == 0) g_y[rr] = N / S + bias[rr & (Y_ - 1)];
}

// ---------------- cross-entropy loss (target arrives int32) --------------
__global__ void loss_kernel(const int* __restrict__ target) {
    __shared__ float sred[256];
    const int tid = threadIdx.x;
    float total = 0.f;
    for (int b = 0; b < B_; b++) {
        const float* row = g_y + (size_t)b * Y_;
        float m = -INFINITY;
        for (int i = tid; i < Y_; i += 256) m = fmaxf(m, row[i]);
        sred[tid] = m; __syncthreads();
        for (int s = 128; s > 0; s >>= 1) {
            if (tid < s) sred[tid] = fmaxf(sred[tid], sred[tid + s]);
            __syncthreads();
        }
        m = sred[0]; __syncthreads();
        float sum = 0.f;
        for (int i = tid; i < Y_; i += 256) sum += __expf(row[i] - m);
        sred[tid] = sum; __syncthreads();
        for (int s = 128; s > 0; s >>= 1) {
            if (tid < s) sred[tid] += sred[tid + s];
            __syncthreads();
        }
        if (tid == 0) total += m + logf(sred[0]) - row[target[b]];
        __syncthreads();
    }
    if (tid == 0) g_loss = total / (float)B_;
}

__global__ void writeout_kernel(float* __restrict__ out, int out_size) {
    const int idx = blockIdx.x * blockDim.x + threadIdx.x;
    const int ny = B_ * Y_;
    if (out_size >= ny + 1) {
        if (idx == 0) out[0] = g_loss;
        if (idx < ny) out[(out_size - ny) + idx] = g_y[idx];
    } else if (out_size == ny) {
        if (idx < ny) out[idx] = g_y[idx];
    } else {
        if (idx == 0 && out_size >= 1) out[0] = g_loss;
    }
}

extern "C" void kernel_launch(void* const* d_in, const int* in_sizes, int n_in,
                              void* d_out, int out_size) {
    const float* x    = (const float*)d_in[0];
    const float* U    = (const float*)d_in[1];
    const float* F    = (const float*)d_in[2];
    const float* bias = (const float*)d_in[3];
    const int*   tg   = (const int*)d_in[4];

    void *Xh, *Uh, *Fh;
    cudaGetSymbolAddress(&Xh, g_Xh);
    cudaGetSymbolAddress(&Uh, g_Uh);
    cudaGetSymbolAddress(&Fh, g_Fh);

    const int nx4 = B_ * L_ * D_ / 4;
    const int nw4 = Y_ * D_ / 4;
    cvt_f16<<<(nx4 + 255) / 256, 256>>>(x, (__half*)Xh, nx4);
    cvt_f16<<<(nw4 + 255) / 256, 256>>>(U, (__half*)Uh, nw4);
    cvt_f16<<<(nw4 + 255) / 256, 256>>>(F, (__half*)Fh, nw4);

    int nsm = 148;
    cudaDeviceGetAttribute(&nsm, cudaDevAttrMultiProcessorCount, 0);
    cudaFuncSetAttribute(gemm_kernel, cudaFuncAttributeMaxDynamicSharedMemorySize, SMEM_TOT);
    gemm_kernel<<<2 * nsm, 256, SMEM_TOT>>>();

    reduce_kernel<<<B_ * Y_ / 8, 256>>>(bias);
    loss_kernel<<<1, 256>>>(tg);
    writeout_kernel<<<(B_ * Y_ + 255) / 256, 256>>>((float*)d_out, out_size);
}

// round 15
// speedup vs baseline: 1.0703x; 1.0703x over previous
#include <cuda_runtime.h>
#include <cuda_fp16.h>
#include <math.h>
#include <stdint.h>

#define B_ 8
#define L_ 4096
#define D_ 768
#define Y_ 2048
#define NLB 32                  // l-blocks (L/128)
#define NTILES 4096             // 32 lblk * 16 yblk * 8 b

// ---------------- device scratch (no allocations allowed) ----------------
__device__ __half g_Xh[(size_t)B_ * L_ * D_];
__device__ __half g_Uh[(size_t)Y_ * D_];
__device__ __half g_Fh[(size_t)Y_ * D_];
__device__ float g_pm[(size_t)B_ * Y_ * NLB];
__device__ float g_ps[(size_t)B_ * Y_ * NLB];
__device__ float g_pn[(size_t)B_ * Y_ * NLB];
__device__ float g_y[(size_t)B_ * Y_];
__device__ unsigned int g_done;

// ---------------- helpers ----------------
__device__ __forceinline__ uint32_t smem_u32(const void* p) {
    uint32_t a;
    asm("{ .reg .u64 t; cvta.to.shared.u64 t, %1; cvt.u32.u64 %0, t; }" : "=r"(a) : "l"(p));
    return a;
}
#define SWZ128(x) ((x) ^ (((x) >> 3) & 0x70))

#define CP16(dst, src) \
    asm volatile("cp.async.cg.shared.global [%0], [%1], 16;" :: "r"(dst), "l"(src))
#define CPCOMMIT() asm volatile("cp.async.commit_group;" ::: "memory")
#define CPWAIT1() asm volatile("cp.async.wait_group 1;" ::: "memory")
#define CPWAIT0() asm volatile("cp.async.wait_group 0;" ::: "memory")

__device__ __forceinline__ void ldsm_x4(uint32_t* r, uint32_t addr) {
    asm volatile("ldmatrix.sync.aligned.m8n8.x4.shared.b16 {%0,%1,%2,%3}, [%4];"
        : "=r"(r[0]), "=r"(r[1]), "=r"(r[2]), "=r"(r[3]) : "r"(addr));
}
#define MMA_F16(d, a, b0, b1)                                                 \
    asm volatile("mma.sync.aligned.m16n8k16.row.col.f32.f16.f16.f32 "         \
        "{%0,%1,%2,%3}, {%4,%5,%6,%7}, {%8,%9}, {%0,%1,%2,%3};"               \
        : "+f"((d)[0]), "+f"((d)[1]), "+f"((d)[2]), "+f"((d)[3])              \
        : "r"((a)[0]), "r"((a)[1]), "r"((a)[2]), "r"((a)[3]),                 \
          "r"(b0), "r"(b1))

// ---------------- fused fp32 -> fp16 convert (x, U, F in one launch) ------
#define NX4 (B_ * L_ * D_ / 4)     // 6291456
#define NW4 (Y_ * D_ / 4)          // 393216
__global__ void cvt_all(const float* __restrict__ x, const float* __restrict__ U,
                        const float* __restrict__ F) {
    int i = blockIdx.x * blockDim.x + threadIdx.x;
    const float* in;
    __half* out;
    int idx;
    if (i < NX4) { in = x; out = g_Xh; idx = i; }
    else if (i < NX4 + NW4) { in = U; out = g_Uh; idx = i - NX4; }
    else if (i < NX4 + 2 * NW4) { in = F; out = g_Fh; idx = i - NX4 - NW4; }
    else return;
    float4 v = ((const float4*)in)[idx];
    ((__half2*)out)[idx * 2 + 0] = __half2(__float2half_rn(v.x), __float2half_rn(v.y));
    ((__half2*)out)[idx * 2 + 1] = __half2(__float2half_rn(v.z), __float2half_rn(v.w));
}

// ------- persistent dual GEMM (pure fp16, 2 MMA/k16) + register softmax ----
// R13 config (confirmed best): 1 CTA/SM, 512 thr, CTA 128y x 128l,
// warp grid 4y x 4l, k-chunk 128 as two 64-col sub-tiles, 2-stage ring.
#define T16K 16384
#define STAGE_B 98304
#define PART_OFF (2 * STAGE_B)     // 196608
#define SMEM_TOT (PART_OFF + 3 * 128 * 4 * 4)   // 202752

__device__ __forceinline__ void issue_stage(uint32_t sb, int ls,
                                            int tid, int stride) {
    const int tl = ls / 6, ks = ls - tl * 6;
    const int t = blockIdx.x + tl * stride;
    const int lblk = t & 31, yblk = (t >> 5) & 15, b = t >> 9;
    const __half* srcs[3] = {
        g_Uh + (size_t)(yblk * 128) * D_,
        g_Fh + (size_t)(yblk * 128) * D_,
        g_Xh + ((size_t)b * L_ + lblk * 128) * D_
    };
    const uint32_t bufb = (uint32_t)(ls & 1) * STAGE_B;
#pragma unroll
    for (int j = 0; j < 12; j++) {
        const int gi = j * 512 + tid;          // 0..6143
        const int tt = gi >> 10;               // sub-tile 0..5
        const int ci = gi & 1023;
        const int row = ci >> 3, c16 = ci & 7;
        const __half* base = srcs[tt >> 1] + (size_t)row * D_ + ks * 128 + (tt & 1) * 64;
        const char* src = (const char*)base + c16 * 16;
        const uint32_t dst = sb + bufb + tt * T16K + SWZ128(row * 128 + c16 * 16);
        CP16(dst, src);
    }
    CPCOMMIT();
}

__global__ void __launch_bounds__(512, 1)
gemm_kernel() {
    extern __shared__ char smem[];
    const uint32_t sb = smem_u32(smem);
    float* partm = (float*)(smem + PART_OFF);          // [128][4]
    float* parts = partm + 128 * 4;
    float* partn = parts + 128 * 4;

    const int tid = threadIdx.x, lane = tid & 31, wid = tid >> 5;
    const int stride = gridDim.x;
    const int myN = (NTILES - blockIdx.x + stride - 1) / stride;
    const int total = 6 * myN;

    const int my = (wid & 3) * 32;
    const int nl = (wid >> 2) * 32;
    const int wcol = wid >> 2;

    // unswizzled byte offsets; SWZ128 applied per load (swizzle not additive)
    const uint32_t aByte = (uint32_t)((my + (lane & 15)) * 128 + ((lane >> 4) << 4));
    const uint32_t bByte = (uint32_t)((nl + (lane & 7) + ((lane >> 4) & 1) * 8) * 128
                                      + (((lane >> 3) & 1) << 4));

    float att[2][4][4], tac[2][4][4];
#pragma unroll
    for (int mt = 0; mt < 2; mt++)
#pragma unroll
        for (int nt = 0; nt < 4; nt++)
#pragma unroll
            for (int r = 0; r < 4; r++) { att[mt][nt][r] = 0.f; tac[mt][nt][r] = 0.f; }

    issue_stage(sb, 0, tid, stride);
    if (total > 1) issue_stage(sb, 1, tid, stride);

    for (int ls = 0; ls < total; ls++) {
        if (ls == total - 1) { CPWAIT0(); } else { CPWAIT1(); }
        __syncthreads();
        const uint32_t bufo = sb + (uint32_t)(ls & 1) * STAGE_B;

#pragma unroll
        for (int kk = 0; kk < 8; kk++) {
            const uint32_t hoff = (uint32_t)(kk >> 2) * T16K;
            const uint32_t kq32 = (uint32_t)((kk & 3) * 32);
            uint32_t bh0[4], bh1[4];
            {
                const uint32_t sw0 = SWZ128(bByte + kq32);
                const uint32_t sw1 = SWZ128(bByte + (uint32_t)(16 * 128) + kq32);
                ldsm_x4(bh0, bufo + 4 * T16K + hoff + sw0);
                ldsm_x4(bh1, bufo + 4 * T16K + hoff + sw1);
            }
#pragma unroll
            for (int mt = 0; mt < 2; mt++) {
                const uint32_t swa = SWZ128(aByte + (uint32_t)(mt * 16 * 128) + kq32);
                uint32_t uh[4], fh[4];
                ldsm_x4(uh, bufo + 0 * T16K + hoff + swa);
                ldsm_x4(fh, bufo + 2 * T16K + hoff + swa);
                MMA_F16(att[mt][0], uh, bh0[0], bh0[1]);
                MMA_F16(att[mt][1], uh, bh0[2], bh0[3]);
                MMA_F16(att[mt][2], uh, bh1[0], bh1[1]);
                MMA_F16(att[mt][3], uh, bh1[2], bh1[3]);
                MMA_F16(tac[mt][0], fh, bh0[0], bh0[1]);
                MMA_F16(tac[mt][1], fh, bh0[2], bh0[3]);
                MMA_F16(tac[mt][2], fh, bh1[0], bh1[1]);
                MMA_F16(tac[mt][3], fh, bh1[2], bh1[3]);
            }
        }
        __syncthreads();
        if (ls + 2 < total) issue_stage(sb, ls + 2, tid, stride);

        if ((ls % 6) == 5) {
            // ---- register-level partial softmax for this 128x128 tile ----
            const int t = blockIdx.x + (ls / 6) * stride;
            const int lblk = t & 31, yblk = (t >> 5) & 15, b = t >> 9;
#pragma unroll
            for (int mt = 0; mt < 2; mt++) {
#pragma unroll
                for (int half = 0; half < 2; half++) {
                    float a[8], tv[8];
#pragma unroll
                    for (int nt = 0; nt < 4; nt++)
#pragma unroll
                        for (int j = 0; j < 2; j++) {
                            a[nt * 2 + j] = att[mt][nt][half * 2 + j];
                            tv[nt * 2 + j] = tac[mt][nt][half * 2 + j];
                        }
                    float m = a[0];
#pragma unroll
                    for (int j = 1; j < 8; j++) m = fmaxf(m, a[j]);
                    m = fmaxf(m, __shfl_xor_sync(0xffffffffu, m, 1));
                    m = fmaxf(m, __shfl_xor_sync(0xffffffffu, m, 2));
                    float S = 0.f, N = 0.f;
#pragma unroll
                    for (int j = 0; j < 8; j++) {
                        const float e = __expf(a[j] - m);
                        S += e;
                        N += e * tv[j];
                    }
                    S += __shfl_xor_sync(0xffffffffu, S, 1);
                    S += __shfl_xor_sync(0xffffffffu, S, 2);
                    N += __shfl_xor_sync(0xffffffffu, N, 1);
                    N += __shfl_xor_sync(0xffffffffu, N, 2);
                    if ((lane & 3) == 0) {
                        const int row = my + mt * 16 + half * 8 + (lane >> 2);
                        partm[row * 4 + wcol] = m;
                        parts[row * 4 + wcol] = S;
                        partn[row * 4 + wcol] = N;
                    }
                }
            }
            __syncthreads();
            if (tid < 128) {
                const float m0 = partm[tid * 4 + 0], m1 = partm[tid * 4 + 1];
                const float m2 = partm[tid * 4 + 2], m3 = partm[tid * 4 + 3];
                const float gm = fmaxf(fmaxf(m0, m1), fmaxf(m2, m3));
                const float e0 = __expf(m0 - gm), e1 = __expf(m1 - gm);
                const float e2 = __expf(m2 - gm), e3 = __expf(m3 - gm);
                const float S = parts[tid * 4 + 0] * e0 + parts[tid * 4 + 1] * e1
                              + parts[tid * 4 + 2] * e2 + parts[tid * 4 + 3] * e3;
                const float N = partn[tid * 4 + 0] * e0 + partn[tid * 4 + 1] * e1
                              + partn[tid * 4 + 2] * e2 + partn[tid * 4 + 3] * e3;
                const size_t idx = ((size_t)b * Y_ + yblk * 128 + tid) * NLB + lblk;
                g_pm[idx] = gm; g_ps[idx] = S; g_pn[idx] = N;
            }
#pragma unroll
            for (int mt = 0; mt < 2; mt++)
#pragma unroll
                for (int nt = 0; nt < 4; nt++)
#pragma unroll
                    for (int r = 0; r < 4; r++) {
                        att[mt][nt][r] = 0.f; tac[mt][nt][r] = 0.f;
                    }
        }
    }
}

// ------- fused finalize: reduce partials -> logits -> (last block) loss ----
// 256 blocks x 256 threads; block handles 8 rows. Each block writes its y rows
// to g_y AND d_out; the last block to finish computes CE loss -> out[0].
__global__ void __launch_bounds__(256)
finalize_kernel(const float* __restrict__ bias, const int* __restrict__ target,
                float* __restrict__ out, int out_size) {
    const int rr = blockIdx.x * 8 + (threadIdx.x >> 5);
    const int lane = threadIdx.x & 31;
    const size_t base = (size_t)rr * NLB + lane;
    const float m = g_pm[base];
    float gm = m;
#pragma unroll
    for (int s = 16; s > 0; s >>= 1) gm = fmaxf(gm, __shfl_xor_sync(0xffffffffu, gm, s));
    const float sc = __expf(m - gm);
    float S = g_ps[base] * sc;
    float N = g_pn[base] * sc;
#pragma unroll
    for (int s = 16; s > 0; s >>= 1) {
        S += __shfl_xor_sync(0xffffffffu, S, s);
        N += __shfl_xor_sync(0xffffffffu, N, s);
    }
    const int ny = B_ * Y_;
    const int yoff = (out_size >= ny + 1) ? (out_size - ny) : 0;
    if (lane == 0) {
        const float yv = N / S + bias[rr & (Y_ - 1)];
        g_y[rr] = yv;
        if (out_size >= ny + 1) out[yoff + rr] = yv;
        else if (out_size == ny) out[rr] = yv;
    }
    // last-block-done: compute loss
    __threadfence();
    __syncthreads();
    __shared__ unsigned int amLast;
    if (threadIdx.x == 0)
        amLast = (atomicAdd(&g_done, 1u) == gridDim.x - 1u);
    __syncthreads();
    if (!amLast) return;
    if (threadIdx.x == 0) g_done = 0;   // reset for next graph replay

    __shared__ float sred[256];
    const int tid = threadIdx.x;
    float total = 0.f;
    for (int b = 0; b < B_; b++) {
        const float* row = g_y + (size_t)b * Y_;
        float mm = -INFINITY;
        for (int i = tid; i < Y_; i += 256) mm = fmaxf(mm, row[i]);
        sred[tid] = mm; __syncthreads();
        for (int s = 128; s > 0; s >>= 1) {
            if (tid < s) sred[tid] = fmaxf(sred[tid], sred[tid + s]);
            __syncthreads();
        }
        mm = sred[0]; __syncthreads();
        float sum = 0.f;
        for (int i = tid; i < Y_; i += 256) sum += __expf(row[i] - mm);
        sred[tid] = sum; __syncthreads();
        for (int s = 128; s > 0; s >>= 1) {
            if (tid < s) sred[tid] += sred[tid + s];
            __syncthreads();
        }
        if (tid == 0) total += mm + logf(sred[0]) - row[target[b]];
        __syncthreads();
    }
    if (tid == 0 && out_size >= 1 && out_size != ny) out[0] = total / (float)B_;
}

extern "C" void kernel_launch(void* const* d_in, const int* in_sizes, int n_in,
                              void* d_out, int out_size) {
    const float* x    = (const float*)d_in[0];
    const float* U    = (const float*)d_in[1];
    const float* F    = (const float*)d_in[2];
    const float* bias = (const float*)d_in[3];
    const int*   tg   = (const int*)d_in[4];

    const int ntot = NX4 + 2 * NW4;
    cvt_all<<<(ntot + 255) / 256, 256>>>(x, U, F);

    int nsm = 148;
    cudaDeviceGetAttribute(&nsm, cudaDevAttrMultiProcessorCount, 0);
    cudaFuncSetAttribute(gemm_kernel, cudaFuncAttributeMaxDynamicSharedMemorySize, SMEM_TOT);
    gemm_kernel<<<nsm, 512, SMEM_TOT>>>();

    finalize_kernel<<<B_ * Y_ / 8, 256>>>(bias, tg, (float*)d_out, out_size);
}